// round 14
// baseline (speedup 1.0000x reference)
#include <cuda_runtime.h>
#include <cuda_fp16.h>
#include <math.h>

#define NN 20000
#define DD 128
#define NE (NN*DD)          // 2,560,000
#define NEDGE 320000
#define ELLW 64
#define LN_EPS 1e-5f
#define LAMW 0.1

// ---------------- device scratch (no allocations allowed) ----------------
// pool: F0..F7 (8), Z7 (1) => 9 * NE floats
__device__ float  g_pool[9*NE];
__device__ uint2  g_zh[2][NE/4];      // ping-pong fp16 mirror of z (gather source)
__device__ int    g_cnt[NN];
__device__ int2   g_ell[NN*ELLW];     // zero-init at load; pads stay {0,0} forever
__device__ double g_red[28];
__device__ float  g_gamma[8];
__device__ int    g_flag[2];

struct Win  { const float4* p[5]; };
struct Arr7 { const float4* p[7]; };

// ---------------- init: zero counts + reductions + flags ----------------
__global__ void k_init() {
    int i = blockIdx.x*blockDim.x + threadIdx.x;
    if (i < NN) g_cnt[i] = 0;
    if (i < 28) g_red[i] = 0.0;
    if (i < 2)  g_flag[i] = 0;
}

// ---------------- single-pass ELL build ----------------
__global__ void k_build(const int* __restrict__ rows, const int* __restrict__ cols,
                        const float* __restrict__ vals) {
    int e = blockIdx.x*blockDim.x + threadIdx.x;
    if (e < NEDGE) {
        int r = rows[e];
        int p = atomicAdd(&g_cnt[r], 1);
        if (p < ELLW)
            g_ell[r*ELLW + p] = make_int2(cols[e], __float_as_int(vals[e]));
    }
}

// ---------------- fp32 -> fp16 mirror (x_init) ----------------
__global__ void k_tohalf(const float4* __restrict__ src, uint2* __restrict__ dst) {
    int i = blockIdx.x*blockDim.x + threadIdx.x;
    if (i < NE/4) {
        float4 v = src[i];
        __half2 h0 = __floats2half2_rn(v.x, v.y);
        __half2 h1 = __floats2half2_rn(v.z, v.w);
        dst[i] = make_uint2(*(unsigned*)&h0, *(unsigned*)&h1);
    }
}

__device__ __forceinline__ void acc_half(float4& acc, float v, uint2 t) {
    float2 f0 = __half22float2(*(__half2*)&t.x);
    float2 f1 = __half22float2(*(__half2*)&t.y);
    acc.x += v*f0.x; acc.y += v*f0.y; acc.z += v*f1.x; acc.w += v*f1.y;
}

// ---------------- fused diag*z + SpMM(fp16 gather) + layernorm ----------------
// R10-proven loop shape + grid-stride over nodes: resident-sized grid, each
// warp handles ~2-3 nodes, self-balancing degree variance and removing
// wave-quantization tail.
__global__ void k_spmm_ln(const float4* __restrict__ z,      // fp32 z (self term)
                          const uint2*  __restrict__ zh,     // fp16 mirror (gather)
                          float4* __restrict__ out,          // F_i fp32
                          uint2*  __restrict__ outh,         // fp16 mirror out (or null)
                          const float* __restrict__ diag,
                          const float4* __restrict__ w4, const float4* __restrict__ b4) {
    int lane   = threadIdx.x & 31;
    int warp0  = (blockIdx.x*blockDim.x + threadIdx.x) >> 5;
    int nwarps = (gridDim.x*blockDim.x) >> 5;

    float4 wv = w4[lane], bv = b4[lane];

    for (int gw = warp0; gw < NN; gw += nwarps) {
        int cnt = g_cnt[gw];
        if (cnt > ELLW) cnt = ELLW;
        int rcnt = (cnt + 7) & ~7;             // padded entries are value-0
        const int4* erow = (const int4*)&g_ell[gw*ELLW];

        float dg  = diag[gw];
        float4 zc = z[gw*32 + lane];
        float4 acc = make_float4(dg*zc.x, dg*zc.y, dg*zc.z, dg*zc.w);

        for (int k = 0; k < rcnt; k += 8) {
            int b = k >> 1;                    // int4 = 2 edges
            int4 e01 = erow[b+0];
            int4 e23 = erow[b+1];
            int4 e45 = erow[b+2];
            int4 e67 = erow[b+3];

            uint2 t0 = zh[e01.x*32 + lane];
            uint2 t1 = zh[e01.z*32 + lane];
            uint2 t2 = zh[e23.x*32 + lane];
            uint2 t3 = zh[e23.z*32 + lane];
            uint2 t4 = zh[e45.x*32 + lane];
            uint2 t5 = zh[e45.z*32 + lane];
            uint2 t6 = zh[e67.x*32 + lane];
            uint2 t7 = zh[e67.z*32 + lane];

            acc_half(acc, __int_as_float(e01.y), t0);
            acc_half(acc, __int_as_float(e01.w), t1);
            acc_half(acc, __int_as_float(e23.y), t2);
            acc_half(acc, __int_as_float(e23.w), t3);
            acc_half(acc, __int_as_float(e45.y), t4);
            acc_half(acc, __int_as_float(e45.w), t5);
            acc_half(acc, __int_as_float(e67.y), t6);
            acc_half(acc, __int_as_float(e67.w), t7);
        }

        // layernorm over the 128-dim row (warp collective)
        float ssum = acc.x + acc.y + acc.z + acc.w;
        #pragma unroll
        for (int off = 16; off; off >>= 1) ssum += __shfl_xor_sync(0xffffffffu, ssum, off);
        float mu = ssum * (1.0f/128.0f);

        float dx = acc.x - mu, dy = acc.y - mu, dz = acc.z - mu, dw = acc.w - mu;
        float vs = dx*dx + dy*dy + dz*dz + dw*dw;
        #pragma unroll
        for (int off = 16; off; off >>= 1) vs += __shfl_xor_sync(0xffffffffu, vs, off);
        float inv = rsqrtf(vs * (1.0f/128.0f) + LN_EPS);

        float4 o = make_float4(wv.x*dx*inv + bv.x, wv.y*dy*inv + bv.y,
                               wv.z*dz*inv + bv.z, wv.w*dw*inv + bv.w);
        out[gw*32 + lane] = o;

        if (outh) {
            __half2 h0 = __floats2half2_rn(o.x, o.y);
            __half2 h1 = __floats2half2_rn(o.z, o.w);
            outh[gw*32 + lane] = make_uint2(*(unsigned*)&h0, *(unsigned*)&h1);
        }
    }
}

// ---------------- Anderson dots: shared reduction tail ----------------
__device__ __forceinline__ void dots_core(const float4 g[5], float s[14]) {
    float4 dgv[4];
    #pragma unroll
    for (int m = 0; m < 4; m++)
        dgv[m] = make_float4(g[m+1].x-g[m].x, g[m+1].y-g[m].y,
                             g[m+1].z-g[m].z, g[m+1].w-g[m].w);
    int c = 0;
    #pragma unroll
    for (int m = 0; m < 4; m++)
        #pragma unroll
        for (int n = m; n < 4; n++)
            s[c++] += dgv[m].x*dgv[n].x + dgv[m].y*dgv[n].y
                    + dgv[m].z*dgv[n].z + dgv[m].w*dgv[n].w;
    #pragma unroll
    for (int m = 0; m < 4; m++)
        s[10+m] += dgv[m].x*g[4].x + dgv[m].y*g[4].y
                 + dgv[m].z*g[4].z + dgv[m].w*g[4].w;
}

__device__ __forceinline__ void dots_reduce(float s[14], int roff) {
    __shared__ float red[14][8];
    int wid = threadIdx.x >> 5, lane = threadIdx.x & 31;
    #pragma unroll
    for (int j = 0; j < 14; j++) {
        float v = s[j];
        #pragma unroll
        for (int off = 16; off; off >>= 1) v += __shfl_xor_sync(0xffffffffu, v, off);
        if (lane == 0) red[j][wid] = v;
    }
    __syncthreads();
    if (threadIdx.x < 14) {
        double t = 0.0;
        #pragma unroll
        for (int k = 0; k < 8; k++) t += (double)red[threadIdx.x][k];
        atomicAdd(&g_red[roff + threadIdx.x], t);
    }
}

// step 0: window j=2..6, z_j = F_{j-1}  =>  G[k] = a[k+1] - a[k], a = {F1..F6}
__global__ void k_dots6(Arr7 A, int roff) {
    float s[14];
    #pragma unroll
    for (int j = 0; j < 14; j++) s[j] = 0.0f;

    int stride = gridDim.x * blockDim.x;
    for (int i = blockIdx.x*blockDim.x + threadIdx.x; i < NE/4; i += stride) {
        float4 a[6];
        #pragma unroll
        for (int k = 0; k < 6; k++) a[k] = A.p[k][i];
        float4 g[5];
        #pragma unroll
        for (int k = 0; k < 5; k++)
            g[k] = make_float4(a[k+1].x-a[k].x, a[k+1].y-a[k].y,
                               a[k+1].z-a[k].z, a[k+1].w-a[k].w);
        dots_core(g, s);
    }
    dots_reduce(s, roff);
}

// step 1: a = {F2,F3,F4,F5,F6,F7,Z7}: G[k]=a[k+1]-a[k] k=0..3, G[4]=a[5]-a[6]
__global__ void k_dots7(Arr7 A, int roff) {
    float s[14];
    #pragma unroll
    for (int j = 0; j < 14; j++) s[j] = 0.0f;

    int stride = gridDim.x * blockDim.x;
    for (int i = blockIdx.x*blockDim.x + threadIdx.x; i < NE/4; i += stride) {
        float4 a[7];
        #pragma unroll
        for (int k = 0; k < 7; k++) a[k] = A.p[k][i];
        float4 g[5];
        #pragma unroll
        for (int k = 0; k < 4; k++)
            g[k] = make_float4(a[k+1].x-a[k].x, a[k+1].y-a[k].y,
                               a[k+1].z-a[k].z, a[k+1].w-a[k].w);
        g[4] = make_float4(a[5].x-a[6].x, a[5].y-a[6].y,
                           a[5].z-a[6].z, a[5].w-a[6].w);
        dots_core(g, s);
    }
    dots_reduce(s, roff);
}

// ---------------- 4x4 solve + gamma finiteness flag ----------------
__global__ void k_solve(int roff, int step) {
    double H[4][4], rhs[4], gam[4];
    int c = 0;
    for (int m = 0; m < 4; m++)
        for (int n = m; n < 4; n++) { H[m][n] = H[n][m] = g_red[roff + c]; c++; }
    for (int m = 0; m < 4; m++) rhs[m] = g_red[roff + 10 + m];
    for (int m = 0; m < 4; m++) H[m][m] += LAMW;

    for (int k = 0; k < 4; k++) {
        int p = k;
        for (int r = k+1; r < 4; r++) if (fabs(H[r][k]) > fabs(H[p][k])) p = r;
        if (p != k) {
            for (int cc = 0; cc < 4; cc++) { double t = H[k][cc]; H[k][cc] = H[p][cc]; H[p][cc] = t; }
            double t = rhs[k]; rhs[k] = rhs[p]; rhs[p] = t;
        }
        for (int r = k+1; r < 4; r++) {
            double fac = H[r][k] / H[k][k];
            for (int cc = k; cc < 4; cc++) H[r][cc] -= fac * H[k][cc];
            rhs[r] -= fac * rhs[k];
        }
    }
    for (int k = 3; k >= 0; k--) {
        double t = rhs[k];
        for (int cc = k+1; cc < 4; cc++) t -= H[k][cc] * gam[cc];
        gam[k] = t / H[k][k];
    }
    int bad = 0;
    for (int m = 0; m < 4; m++) {
        if (!isfinite(gam[m])) bad = 1;
        g_gamma[step*4 + m] = (float)gam[m];
    }
    g_flag[step] = bad;   // F finite (layernorm-bounded) => z_new nonfinite iff gamma is
}

// ---------------- fused z_new + blend (+ optional fp16 mirror) ----------------
// out = flag ? F4 : F4 - 0.5 * sum_m gamma_m * (F[m+1]-F[m])
__global__ void k_znew_blend(Win F, int step, float4* __restrict__ out,
                             uint2* __restrict__ outh) {
    float gm[4];
    int flag = g_flag[step];
    #pragma unroll
    for (int m = 0; m < 4; m++) gm[m] = 0.5f * g_gamma[step*4 + m];

    int stride = gridDim.x * blockDim.x;
    for (int i = blockIdx.x*blockDim.x + threadIdx.x; i < NE/4; i += stride) {
        float4 f[5];
        #pragma unroll
        for (int k = 0; k < 5; k++) f[k] = F.p[k][i];
        float4 a = f[4];
        if (!flag) {
            #pragma unroll
            for (int m = 0; m < 4; m++) {
                a.x -= gm[m] * (f[m+1].x - f[m].x);
                a.y -= gm[m] * (f[m+1].y - f[m].y);
                a.z -= gm[m] * (f[m+1].z - f[m].z);
                a.w -= gm[m] * (f[m+1].w - f[m].w);
            }
        }
        out[i] = a;
        if (outh) {
            __half2 h0 = __floats2half2_rn(a.x, a.y);
            __half2 h1 = __floats2half2_rn(a.z, a.w);
            outh[i] = make_uint2(*(unsigned*)&h0, *(unsigned*)&h1);
        }
    }
}

// ---------------- host ----------------
extern "C" void kernel_launch(void* const* d_in, const int* in_sizes, int n_in,
                              void* d_out, int out_size) {
    const float*  x    = (const float*)d_in[0];
    const float*  diag = (const float*)d_in[1];
    const float*  vals = (const float*)d_in[2];
    const float4* w4   = (const float4*)d_in[3];
    const float4* b4   = (const float4*)d_in[4];
    const int*    rows = (const int*)d_in[5];
    const int*    cols = (const int*)d_in[6];

    float* pool = nullptr;
    cudaGetSymbolAddress((void**)&pool, g_pool);
    uint2* zh = nullptr;
    cudaGetSymbolAddress((void**)&zh, g_zh);
    uint2* hb[2] = { zh, zh + NE/4 };

    float* F[8];
    for (int i = 0; i < 8; i++) F[i] = pool + (size_t)i * NE;
    float* Z7 = pool + (size_t)8 * NE;

    k_init  <<<(NN+255)/256, 256>>>();
    k_build <<<(NEDGE+255)/256, 256>>>(rows, cols, vals);
    k_tohalf<<<(NE/4+255)/256, 256>>>((const float4*)x, hb[0]);

    const float* z = x;
    for (int i = 0; i < 8; i++) {
        uint2* outh = (i < 6) ? hb[(i+1)&1] : nullptr;
        k_spmm_ln<<<1184, 256>>>((const float4*)z, hb[i&1],
                                 (float4*)F[i], outh, diag, w4, b4);
        if (i < 6) {
            z = F[i];
        } else {
            int step = i - 6;
            if (step == 0) {
                Arr7 A;
                for (int k = 0; k < 6; k++) A.p[k] = (const float4*)F[1+k]; // F1..F6
                A.p[6] = nullptr;
                k_dots6<<<1184, 256>>>(A, 0);
            } else {
                Arr7 A;
                for (int k = 0; k < 6; k++) A.p[k] = (const float4*)F[2+k]; // F2..F7
                A.p[6] = (const float4*)Z7;
                k_dots7<<<1184, 256>>>(A, 14);
            }
            k_solve<<<1, 1>>>(step*14, step);
            Win fw;
            for (int k = 0; k < 5; k++) fw.p[k] = (const float4*)F[i-4+k];
            float* dst = (i == 7) ? (float*)d_out : Z7;
            uint2* dsth = (i == 6) ? hb[(i+1)&1] : nullptr;
            k_znew_blend<<<1184, 256>>>(fw, step, (float4*)dst, dsth);
            z = dst;
        }
    }
}

// round 15
// speedup vs baseline: 1.2230x; 1.2230x over previous
#include <cuda_runtime.h>
#include <cuda_fp16.h>
#include <math.h>

#define NN 20000
#define DD 128
#define NE (NN*DD)          // 2,560,000
#define NEDGE 320000
#define ELLW 64
#define LN_EPS 1e-5f
#define LAMW 0.1

// ---------------- device scratch (no allocations allowed) ----------------
// pool: F0..F7 (8), Z7 (1) => 9 * NE floats
__device__ float  g_pool[9*NE];
__device__ uint2  g_zh[2][NE/4];      // ping-pong fp16 mirror of z (gather source)
__device__ int    g_cnt[NN];
__device__ int2   g_ell[NN*ELLW];     // zero-init at load; pads stay {0,0} forever
__device__ double g_red[28];
__device__ float  g_gamma[8];
__device__ int    g_flag[2];

struct Win  { const float4* p[5]; };
struct Arr7 { const float4* p[7]; };

// ---------------- fused init + fp32->fp16 mirror of x_init ----------------
// zeroes counts/reductions/flags AND builds the iteration-0 fp16 mirror in one
// launch (covers NE/4 = 640000 threads > NN).
__global__ void k_init_tohalf(const float4* __restrict__ src, uint2* __restrict__ dst) {
    int i = blockIdx.x*blockDim.x + threadIdx.x;
    if (i < NE/4) {
        float4 v = src[i];
        __half2 h0 = __floats2half2_rn(v.x, v.y);
        __half2 h1 = __floats2half2_rn(v.z, v.w);
        dst[i] = make_uint2(*(unsigned*)&h0, *(unsigned*)&h1);
    }
    if (i < NN) g_cnt[i] = 0;
    if (i < 28) g_red[i] = 0.0;
    if (i < 2)  g_flag[i] = 0;
}

// ---------------- single-pass ELL build ----------------
__global__ void k_build(const int* __restrict__ rows, const int* __restrict__ cols,
                        const float* __restrict__ vals) {
    int e = blockIdx.x*blockDim.x + threadIdx.x;
    if (e < NEDGE) {
        int r = rows[e];
        int p = atomicAdd(&g_cnt[r], 1);
        if (p < ELLW)
            g_ell[r*ELLW + p] = make_int2(cols[e], __float_as_int(vals[e]));
    }
}

__device__ __forceinline__ void acc_half(float4& acc, float v, uint2 t) {
    float2 f0 = __half22float2(*(__half2*)&t.x);
    float2 f1 = __half22float2(*(__half2*)&t.y);
    acc.x += v*f0.x; acc.y += v*f0.y; acc.z += v*f1.x; acc.w += v*f1.y;
}

// ---------------- fused diag*z + SpMM(fp16 gather) + layernorm ----------------
// R10-proven best shape (DO NOT restructure: every variant regressed):
// one warp/node, grid 2500, warp-uniform int4 edge loads, 8-edge batches,
// fp16 LDG.64 gathers, natural 32-reg allocation.
__global__ void k_spmm_ln(const float4* __restrict__ z,      // fp32 z (self term)
                          const uint2*  __restrict__ zh,     // fp16 mirror (gather)
                          float4* __restrict__ out,          // F_i fp32
                          uint2*  __restrict__ outh,         // fp16 mirror out (or null)
                          const float* __restrict__ diag,
                          const float4* __restrict__ w4, const float4* __restrict__ b4) {
    int gw   = (blockIdx.x*blockDim.x + threadIdx.x) >> 5;
    int lane = threadIdx.x & 31;
    if (gw >= NN) return;

    int cnt = g_cnt[gw];
    if (cnt > ELLW) cnt = ELLW;
    int rcnt = (cnt + 7) & ~7;             // padded entries are value-0
    const int4* erow = (const int4*)&g_ell[gw*ELLW];

    float dg  = diag[gw];
    float4 zc = z[gw*32 + lane];
    float4 acc = make_float4(dg*zc.x, dg*zc.y, dg*zc.z, dg*zc.w);

    for (int k = 0; k < rcnt; k += 8) {
        int b = k >> 1;                    // int4 = 2 edges
        int4 e01 = erow[b+0];
        int4 e23 = erow[b+1];
        int4 e45 = erow[b+2];
        int4 e67 = erow[b+3];

        uint2 t0 = zh[e01.x*32 + lane];
        uint2 t1 = zh[e01.z*32 + lane];
        uint2 t2 = zh[e23.x*32 + lane];
        uint2 t3 = zh[e23.z*32 + lane];
        uint2 t4 = zh[e45.x*32 + lane];
        uint2 t5 = zh[e45.z*32 + lane];
        uint2 t6 = zh[e67.x*32 + lane];
        uint2 t7 = zh[e67.z*32 + lane];

        acc_half(acc, __int_as_float(e01.y), t0);
        acc_half(acc, __int_as_float(e01.w), t1);
        acc_half(acc, __int_as_float(e23.y), t2);
        acc_half(acc, __int_as_float(e23.w), t3);
        acc_half(acc, __int_as_float(e45.y), t4);
        acc_half(acc, __int_as_float(e45.w), t5);
        acc_half(acc, __int_as_float(e67.y), t6);
        acc_half(acc, __int_as_float(e67.w), t7);
    }

    // layernorm over the 128-dim row (warp collective)
    float ssum = acc.x + acc.y + acc.z + acc.w;
    #pragma unroll
    for (int off = 16; off; off >>= 1) ssum += __shfl_xor_sync(0xffffffffu, ssum, off);
    float mu = ssum * (1.0f/128.0f);

    float dx = acc.x - mu, dy = acc.y - mu, dz = acc.z - mu, dw = acc.w - mu;
    float vs = dx*dx + dy*dy + dz*dz + dw*dw;
    #pragma unroll
    for (int off = 16; off; off >>= 1) vs += __shfl_xor_sync(0xffffffffu, vs, off);
    float inv = rsqrtf(vs * (1.0f/128.0f) + LN_EPS);

    float4 wv = w4[lane], bv = b4[lane];
    float4 o = make_float4(wv.x*dx*inv + bv.x, wv.y*dy*inv + bv.y,
                           wv.z*dz*inv + bv.z, wv.w*dw*inv + bv.w);
    out[gw*32 + lane] = o;

    if (outh) {
        __half2 h0 = __floats2half2_rn(o.x, o.y);
        __half2 h1 = __floats2half2_rn(o.z, o.w);
        outh[gw*32 + lane] = make_uint2(*(unsigned*)&h0, *(unsigned*)&h1);
    }
}

// ---------------- Anderson dots: shared reduction tail ----------------
__device__ __forceinline__ void dots_core(const float4 g[5], float s[14]) {
    float4 dgv[4];
    #pragma unroll
    for (int m = 0; m < 4; m++)
        dgv[m] = make_float4(g[m+1].x-g[m].x, g[m+1].y-g[m].y,
                             g[m+1].z-g[m].z, g[m+1].w-g[m].w);
    int c = 0;
    #pragma unroll
    for (int m = 0; m < 4; m++)
        #pragma unroll
        for (int n = m; n < 4; n++)
            s[c++] += dgv[m].x*dgv[n].x + dgv[m].y*dgv[n].y
                    + dgv[m].z*dgv[n].z + dgv[m].w*dgv[n].w;
    #pragma unroll
    for (int m = 0; m < 4; m++)
        s[10+m] += dgv[m].x*g[4].x + dgv[m].y*g[4].y
                 + dgv[m].z*g[4].z + dgv[m].w*g[4].w;
}

__device__ __forceinline__ void dots_reduce(float s[14], int roff) {
    __shared__ float red[14][8];
    int wid = threadIdx.x >> 5, lane = threadIdx.x & 31;
    #pragma unroll
    for (int j = 0; j < 14; j++) {
        float v = s[j];
        #pragma unroll
        for (int off = 16; off; off >>= 1) v += __shfl_xor_sync(0xffffffffu, v, off);
        if (lane == 0) red[j][wid] = v;
    }
    __syncthreads();
    if (threadIdx.x < 14) {
        double t = 0.0;
        #pragma unroll
        for (int k = 0; k < 8; k++) t += (double)red[threadIdx.x][k];
        atomicAdd(&g_red[roff + threadIdx.x], t);
    }
}

// step 0: window j=2..6, z_j = F_{j-1}  =>  G[k] = a[k+1] - a[k], a = {F1..F6}
__global__ void k_dots6(Arr7 A, int roff) {
    float s[14];
    #pragma unroll
    for (int j = 0; j < 14; j++) s[j] = 0.0f;

    int stride = gridDim.x * blockDim.x;
    for (int i = blockIdx.x*blockDim.x + threadIdx.x; i < NE/4; i += stride) {
        float4 a[6];
        #pragma unroll
        for (int k = 0; k < 6; k++) a[k] = A.p[k][i];
        float4 g[5];
        #pragma unroll
        for (int k = 0; k < 5; k++)
            g[k] = make_float4(a[k+1].x-a[k].x, a[k+1].y-a[k].y,
                               a[k+1].z-a[k].z, a[k+1].w-a[k].w);
        dots_core(g, s);
    }
    dots_reduce(s, roff);
}

// step 1: a = {F2,F3,F4,F5,F6,F7,Z7}: G[k]=a[k+1]-a[k] k=0..3, G[4]=a[5]-a[6]
__global__ void k_dots7(Arr7 A, int roff) {
    float s[14];
    #pragma unroll
    for (int j = 0; j < 14; j++) s[j] = 0.0f;

    int stride = gridDim.x * blockDim.x;
    for (int i = blockIdx.x*blockDim.x + threadIdx.x; i < NE/4; i += stride) {
        float4 a[7];
        #pragma unroll
        for (int k = 0; k < 7; k++) a[k] = A.p[k][i];
        float4 g[5];
        #pragma unroll
        for (int k = 0; k < 4; k++)
            g[k] = make_float4(a[k+1].x-a[k].x, a[k+1].y-a[k].y,
                               a[k+1].z-a[k].z, a[k+1].w-a[k].w);
        g[4] = make_float4(a[5].x-a[6].x, a[5].y-a[6].y,
                           a[5].z-a[6].z, a[5].w-a[6].w);
        dots_core(g, s);
    }
    dots_reduce(s, roff);
}

// ---------------- 4x4 solve + gamma finiteness flag ----------------
__global__ void k_solve(int roff, int step) {
    double H[4][4], rhs[4], gam[4];
    int c = 0;
    for (int m = 0; m < 4; m++)
        for (int n = m; n < 4; n++) { H[m][n] = H[n][m] = g_red[roff + c]; c++; }
    for (int m = 0; m < 4; m++) rhs[m] = g_red[roff + 10 + m];
    for (int m = 0; m < 4; m++) H[m][m] += LAMW;

    for (int k = 0; k < 4; k++) {
        int p = k;
        for (int r = k+1; r < 4; r++) if (fabs(H[r][k]) > fabs(H[p][k])) p = r;
        if (p != k) {
            for (int cc = 0; cc < 4; cc++) { double t = H[k][cc]; H[k][cc] = H[p][cc]; H[p][cc] = t; }
            double t = rhs[k]; rhs[k] = rhs[p]; rhs[p] = t;
        }
        for (int r = k+1; r < 4; r++) {
            double fac = H[r][k] / H[k][k];
            for (int cc = k; cc < 4; cc++) H[r][cc] -= fac * H[k][cc];
            rhs[r] -= fac * rhs[k];
        }
    }
    for (int k = 3; k >= 0; k--) {
        double t = rhs[k];
        for (int cc = k+1; cc < 4; cc++) t -= H[k][cc] * gam[cc];
        gam[k] = t / H[k][k];
    }
    int bad = 0;
    for (int m = 0; m < 4; m++) {
        if (!isfinite(gam[m])) bad = 1;
        g_gamma[step*4 + m] = (float)gam[m];
    }
    g_flag[step] = bad;   // F finite (layernorm-bounded) => z_new nonfinite iff gamma is
}

// ---------------- fused z_new + blend (+ optional fp16 mirror) ----------------
// out = flag ? F4 : F4 - 0.5 * sum_m gamma_m * (F[m+1]-F[m])
__global__ void k_znew_blend(Win F, int step, float4* __restrict__ out,
                             uint2* __restrict__ outh) {
    float gm[4];
    int flag = g_flag[step];
    #pragma unroll
    for (int m = 0; m < 4; m++) gm[m] = 0.5f * g_gamma[step*4 + m];

    int stride = gridDim.x * blockDim.x;
    for (int i = blockIdx.x*blockDim.x + threadIdx.x; i < NE/4; i += stride) {
        float4 f[5];
        #pragma unroll
        for (int k = 0; k < 5; k++) f[k] = F.p[k][i];
        float4 a = f[4];
        if (!flag) {
            #pragma unroll
            for (int m = 0; m < 4; m++) {
                a.x -= gm[m] * (f[m+1].x - f[m].x);
                a.y -= gm[m] * (f[m+1].y - f[m].y);
                a.z -= gm[m] * (f[m+1].z - f[m].z);
                a.w -= gm[m] * (f[m+1].w - f[m].w);
            }
        }
        out[i] = a;
        if (outh) {
            __half2 h0 = __floats2half2_rn(a.x, a.y);
            __half2 h1 = __floats2half2_rn(a.z, a.w);
            outh[i] = make_uint2(*(unsigned*)&h0, *(unsigned*)&h1);
        }
    }
}

// ---------------- host ----------------
extern "C" void kernel_launch(void* const* d_in, const int* in_sizes, int n_in,
                              void* d_out, int out_size) {
    const float*  x    = (const float*)d_in[0];
    const float*  diag = (const float*)d_in[1];
    const float*  vals = (const float*)d_in[2];
    const float4* w4   = (const float4*)d_in[3];
    const float4* b4   = (const float4*)d_in[4];
    const int*    rows = (const int*)d_in[5];
    const int*    cols = (const int*)d_in[6];

    float* pool = nullptr;
    cudaGetSymbolAddress((void**)&pool, g_pool);
    uint2* zh = nullptr;
    cudaGetSymbolAddress((void**)&zh, g_zh);
    uint2* hb[2] = { zh, zh + NE/4 };

    float* F[8];
    for (int i = 0; i < 8; i++) F[i] = pool + (size_t)i * NE;
    float* Z7 = pool + (size_t)8 * NE;

    k_init_tohalf<<<(NE/4+255)/256, 256>>>((const float4*)x, hb[0]);
    k_build      <<<(NEDGE+255)/256, 256>>>(rows, cols, vals);

    const float* z = x;
    for (int i = 0; i < 8; i++) {
        uint2* outh = (i < 6) ? hb[(i+1)&1] : nullptr;
        k_spmm_ln<<<(NN*32+255)/256, 256>>>((const float4*)z, hb[i&1],
                                            (float4*)F[i], outh, diag, w4, b4);
        if (i < 6) {
            z = F[i];
        } else {
            int step = i - 6;
            if (step == 0) {
                Arr7 A;
                for (int k = 0; k < 6; k++) A.p[k] = (const float4*)F[1+k]; // F1..F6
                A.p[6] = nullptr;
                k_dots6<<<1184, 256>>>(A, 0);
            } else {
                Arr7 A;
                for (int k = 0; k < 6; k++) A.p[k] = (const float4*)F[2+k]; // F2..F7
                A.p[6] = (const float4*)Z7;
                k_dots7<<<1184, 256>>>(A, 14);
            }
            k_solve<<<1, 1>>>(step*14, step);
            Win fw;
            for (int k = 0; k < 5; k++) fw.p[k] = (const float4*)F[i-4+k];
            float* dst = (i == 7) ? (float*)d_out : Z7;
            uint2* dsth = (i == 6) ? hb[(i+1)&1] : nullptr;
            k_znew_blend<<<1184, 256>>>(fw, step, (float4*)dst, dsth);
            z = dst;
        }
    }
}